// round 1
// baseline (speedup 1.0000x reference)
#include <cuda_runtime.h>

#define H_IN 512
#define W_IN 512
#define H_OUT 512
#define W_OUT 512
#define HW (H_IN * W_IN)
#define BC 96   // 32 batch * 3 channels

// max_r = log(norm(512,512)/2 * 2.0) = log(512*sqrt(2)) = 9*ln2 + 0.5*ln2
#define MAX_R 6.58489821531948f
// float32(pi)
#define PI_F 3.14159265358979323846f

__global__ __launch_bounds__(256) void logpolar_kernel(
    const float* __restrict__ in, float* __restrict__ out)
{
    const int pix = blockIdx.x * blockDim.x + threadIdx.x;
    if (pix >= HW) return;

    const int h = pix >> 9;    // theta index (output row)
    const int w = pix & 511;   // r index (output col)

    // Match reference rounding:
    //   ang    = (theta * 2.0 * pi) / 512   -> (2h exact) * pi (1 rnd) * 2^-9 (exact)
    //   radius = exp((r * max_r) / 512)     -> (w * max_r) (1 rnd) * 2^-9 (exact)
    const float ang = (float)(2 * h) * PI_F * (1.0f / 512.0f);
    const float radius = expf((float)w * MAX_R * (1.0f / 512.0f));

    float s, c;
    sincosf(ang, &s, &c);

    const float X = 256.0f + radius * c;
    const float Y = 256.0f - radius * s;

    const bool mask = (X >= 0.0f) && (X < 512.0f) && (Y >= 0.0f) && (Y < 512.0f);

    if (mask) {
        // trunc toward zero (matches .astype(int32)), then clamp
        int y_down = (int)Y; y_down = min(max(y_down, 0), H_IN - 1);
        int x_down = (int)X; x_down = min(max(x_down, 0), W_IN - 1);
        const int y_up = min(y_down + 1, H_IN - 1);
        const int x_up = min(x_down + 1, W_IN - 1);

        const float yd = Y - (float)y_down;
        const float yu = Y - (float)y_up;
        const float xd = X - (float)x_down;
        const float xu = X - (float)x_up;

        const float dd = yd * yd + xd * xd;
        const float du = yd * yd + xu * xu;
        const float ud = yu * yu + xd * xd;
        const float uu = yu * yu + xu * xu;
        const float total = dd + du + ud + uu;

        const float w00 = dd / total;
        const float w01 = du / total;
        const float w10 = ud / total;
        const float w11 = uu / total;

        const int o00 = y_down * W_IN + x_down;
        const int o01 = y_down * W_IN + x_up;
        const int o10 = y_up * W_IN + x_down;
        const int o11 = y_up * W_IN + x_up;

        const float* p = in;
        float* q = out + pix;
        #pragma unroll 4
        for (int bc = 0; bc < BC; ++bc) {
            float v = w00 * __ldg(p + o00)
                    + w01 * __ldg(p + o01)
                    + w10 * __ldg(p + o10)
                    + w11 * __ldg(p + o11);
            *q = v;
            p += HW;
            q += HW;
        }
    } else {
        float* q = out + pix;
        #pragma unroll 8
        for (int bc = 0; bc < BC; ++bc) {
            *q = 0.0f;
            q += HW;
        }
    }
}

extern "C" void kernel_launch(void* const* d_in, const int* in_sizes, int n_in,
                              void* d_out, int out_size)
{
    const float* data = (const float*)d_in[0];
    float* out = (float*)d_out;
    const int threads = 256;
    const int blocks = (HW + threads - 1) / threads;  // 1024
    logpolar_kernel<<<blocks, threads>>>(data, out);
}

// round 2
// speedup vs baseline: 1.4447x; 1.4447x over previous
#include <cuda_runtime.h>

#define H_IN 512
#define W_IN 512
#define HW (H_IN * W_IN)
#define BC 96            // 32 batch * 3 channels
#define BC_PER_THREAD 8
#define BC_CHUNKS (BC / BC_PER_THREAD)   // 12

// max_r = log(norm(512,512)/2 * 2.0) = log(512*sqrt(2))
#define MAX_R 6.58489821531948f
#define PI_F 3.14159265358979323846f

__global__ __launch_bounds__(256) void logpolar_kernel(
    const float* __restrict__ in, float* __restrict__ out)
{
    const int pix = blockIdx.x * blockDim.x + threadIdx.x;
    const int bc0 = blockIdx.y * BC_PER_THREAD;

    const int h = pix >> 9;    // theta index (output row)
    const int w = pix & 511;   // r index (output col)

    // Match reference fp32 rounding:
    //   ang    = (2h exact) * pi (1 rnd) * 2^-9 (exact)
    //   radius = exp((w * max_r) (1 rnd) * 2^-9 (exact))
    const float ang = (float)(2 * h) * PI_F * (1.0f / 512.0f);
    const float radius = expf((float)w * MAX_R * (1.0f / 512.0f));

    float s, c;
    sincosf(ang, &s, &c);

    const float X = 256.0f + radius * c;
    const float Y = 256.0f - radius * s;

    const bool mask = (X >= 0.0f) && (X < 512.0f) && (Y >= 0.0f) && (Y < 512.0f);

    if (mask) {
        // trunc toward zero (matches .astype(int32)), then clamp
        int y_down = (int)Y; y_down = min(max(y_down, 0), H_IN - 1);
        int x_down = (int)X; x_down = min(max(x_down, 0), W_IN - 1);
        const int y_up = min(y_down + 1, H_IN - 1);
        const int x_up = min(x_down + 1, W_IN - 1);

        const float yd = Y - (float)y_down;
        const float yu = Y - (float)y_up;
        const float xd = X - (float)x_down;
        const float xu = X - (float)x_up;

        const float dd = yd * yd + xd * xd;
        const float du = yd * yd + xu * xu;
        const float ud = yu * yu + xd * xd;
        const float uu = yu * yu + xu * xu;
        const float total = dd + du + ud + uu;
        const float inv_total = 1.0f / total;

        const float w00 = dd * inv_total;
        const float w01 = du * inv_total;
        const float w10 = ud * inv_total;
        const float w11 = uu * inv_total;

        const int o00 = y_down * W_IN + x_down;
        const int o01 = y_down * W_IN + x_up;
        const int o10 = y_up * W_IN + x_down;
        const int o11 = y_up * W_IN + x_up;

        const float* p = in + (size_t)bc0 * HW;
        float* q = out + (size_t)bc0 * HW + pix;

        // Fully unrolled: 32 independent LDGs batched up front for MLP.
        float v00[BC_PER_THREAD], v01[BC_PER_THREAD], v10[BC_PER_THREAD], v11[BC_PER_THREAD];
        #pragma unroll
        for (int i = 0; i < BC_PER_THREAD; ++i) {
            const float* pi_ = p + (size_t)i * HW;
            v00[i] = __ldg(pi_ + o00);
            v01[i] = __ldg(pi_ + o01);
            v10[i] = __ldg(pi_ + o10);
            v11[i] = __ldg(pi_ + o11);
        }
        #pragma unroll
        for (int i = 0; i < BC_PER_THREAD; ++i) {
            q[(size_t)i * HW] = w00 * v00[i] + w01 * v01[i]
                              + w10 * v10[i] + w11 * v11[i];
        }
    } else {
        float* q = out + (size_t)bc0 * HW + pix;
        #pragma unroll
        for (int i = 0; i < BC_PER_THREAD; ++i) {
            q[(size_t)i * HW] = 0.0f;
        }
    }
}

extern "C" void kernel_launch(void* const* d_in, const int* in_sizes, int n_in,
                              void* d_out, int out_size)
{
    const float* data = (const float*)d_in[0];
    float* out = (float*)d_out;
    dim3 grid(HW / 256, BC_CHUNKS);   // (1024, 12)
    logpolar_kernel<<<grid, 256>>>(data, out);
}

// round 3
// speedup vs baseline: 1.7866x; 1.2367x over previous
#include <cuda_runtime.h>

#define H_IN 512
#define W_IN 512
#define HW (H_IN * W_IN)
#define BC 96            // 32 batch * 3 channels
#define BC_PER_THREAD 4
#define BC_CHUNKS (BC / BC_PER_THREAD)   // 24

// max_r = log(norm(512,512)/2 * 2.0) = log(512*sqrt(2))
#define MAX_R 6.58489821531948f
#define PI_F 3.14159265358979323846f

__global__ __launch_bounds__(256) void logpolar_kernel(
    const float* __restrict__ in, float* __restrict__ out)
{
    const int pix = blockIdx.x * blockDim.x + threadIdx.x;
    const int bc0 = blockIdx.y * BC_PER_THREAD;

    const int h = pix >> 9;    // theta index (output row)
    const int w = pix & 511;   // r index (output col)

    // Match reference fp32 rounding:
    //   ang    = (2h exact) * pi (1 rnd) * 2^-9 (exact)
    //   radius = exp((w * max_r) (1 rnd) * 2^-9 (exact))
    const float ang = (float)(2 * h) * PI_F * (1.0f / 512.0f);
    const float radius = expf((float)w * MAX_R * (1.0f / 512.0f));

    float s, c;
    sincosf(ang, &s, &c);

    const float X = 256.0f + radius * c;
    const float Y = 256.0f - radius * s;

    const bool mask = (X >= 0.0f) && (X < 512.0f) && (Y >= 0.0f) && (Y < 512.0f);

    if (mask) {
        // trunc toward zero (matches .astype(int32)), then clamp
        int y_down = (int)Y; y_down = min(max(y_down, 0), H_IN - 1);
        int x_down = (int)X; x_down = min(max(x_down, 0), W_IN - 1);
        const int y_up = min(y_down + 1, H_IN - 1);
        const int x_up = min(x_down + 1, W_IN - 1);

        const float yd = Y - (float)y_down;
        const float yu = Y - (float)y_up;
        const float xd = X - (float)x_down;
        const float xu = X - (float)x_up;

        const float dd = yd * yd + xd * xd;
        const float du = yd * yd + xu * xu;
        const float ud = yu * yu + xd * xd;
        const float uu = yu * yu + xu * xu;
        const float total = dd + du + ud + uu;
        const float inv_total = 1.0f / total;

        const float w00 = dd * inv_total;
        const float w01 = du * inv_total;
        const float w10 = ud * inv_total;
        const float w11 = uu * inv_total;

        // Aligned float2 per row covers (x_down, x_down+1) when x_down even.
        const int  xb  = x_down & ~1;
        const bool odd = (x_down & 1) != 0;
        const int  o0  = y_down * W_IN + xb;     // row y_down, aligned pair
        const int  o1  = y_up   * W_IN + xb;     // row y_up,   aligned pair
        const int  oe0 = y_down * W_IN + x_up;   // extra tap when odd
        const int  oe1 = y_up   * W_IN + x_up;

        const float* p = in + (size_t)bc0 * HW;
        float* q = out + (size_t)bc0 * HW + pix;

        // Batch all loads up front for MLP.
        float2 a[BC_PER_THREAD], b[BC_PER_THREAD];
        float  e0[BC_PER_THREAD], e1[BC_PER_THREAD];
        #pragma unroll
        for (int i = 0; i < BC_PER_THREAD; ++i) {
            const float* pi_ = p + (size_t)i * HW;
            a[i] = __ldg((const float2*)(pi_ + o0));
            b[i] = __ldg((const float2*)(pi_ + o1));
            if (odd) {
                e0[i] = __ldg(pi_ + oe0);
                e1[i] = __ldg(pi_ + oe1);
            }
        }
        #pragma unroll
        for (int i = 0; i < BC_PER_THREAD; ++i) {
            const float v00 = odd ? a[i].y : a[i].x;
            const float v01 = odd ? e0[i]  : a[i].y;
            const float v10 = odd ? b[i].y : b[i].x;
            const float v11 = odd ? e1[i]  : b[i].y;
            q[(size_t)i * HW] = w00 * v00 + w01 * v01
                              + w10 * v10 + w11 * v11;
        }
    } else {
        float* q = out + (size_t)bc0 * HW + pix;
        #pragma unroll
        for (int i = 0; i < BC_PER_THREAD; ++i) {
            q[(size_t)i * HW] = 0.0f;
        }
    }
}

extern "C" void kernel_launch(void* const* d_in, const int* in_sizes, int n_in,
                              void* d_out, int out_size)
{
    const float* data = (const float*)d_in[0];
    float* out = (float*)d_out;
    dim3 grid(HW / 256, BC_CHUNKS);   // (1024, 24)
    logpolar_kernel<<<grid, 256>>>(data, out);
}